// round 13
// baseline (speedup 1.0000x reference)
#include <cuda_runtime.h>

typedef unsigned long long ull;

#define FMA2(d, a, bb, c) \
    asm("fma.rn.f32x2 %0, %1, %2, %3;" : "=l"(d) : "l"(a), "l"(bb), "l"(c))
#define MUL2(d, a, bb) \
    asm("mul.rn.f32x2 %0, %1, %2;" : "=l"(d) : "l"(a), "l"(bb))
#define PACK2(d, lo, hi) \
    asm("mov.b64 %0, {%1, %2};" : "=l"(d) : "f"(lo), "f"(hi))
#define UNPACK2(lo, hi, s) \
    asm("mov.b64 {%0, %1}, %2;" : "=f"(lo), "=f"(hi) : "l"(s))

#define NS   86
#define DM   64
#define NH   4
#define HDIM 16
#define NFEAT 11
#define NR   7
#define NT   256
#define BINF (2*NS)

// duplicated weight scratch: g_Wd[2*i]=g_Wd[2*i+1]=Wqkv[i], same for Wa
__device__ __align__(16) float g_Wd[64*192*2];
__device__ __align__(16) float g_Wad[64*64*2];

__global__ void prep_kernel(const float* __restrict__ Wqkv,
                            const float* __restrict__ Wa)
{
    int i = blockIdx.x * blockDim.x + threadIdx.x;   // 16384 threads
    if (i < 64*192) {
        float v = Wqkv[i];
        g_Wd[2*i] = v; g_Wd[2*i + 1] = v;
    } else {
        int t = i - 64*192;
        float v = Wa[t];
        g_Wad[2*t] = v; g_Wad[2*t + 1] = v;
    }
}

// smem float offsets (Wqkv / Wa streamed from L2, not staged)
#define OFF_WC    0        // 832
#define OFF_BC    832      // 64
#define OFF_BQKV  896      // 192
#define OFF_BA    1088     // 64
#define OFF_STAT  1152     // 948
#define OFF_INF   2100     // 172
#define OFF_RID   2272     // 88
#define OFF_CNT   2360     // 8
#define OFF_TOK   2368     // tokT / ctxT: 64*88 = 5632
#define OFF_QKV   8000     // 88*192 = 16896 (reused as attn_out)
#define OFF_CAT   24896    // 512
#define OFF_PART  25408    // 1024
#define SMEM_FLOATS 26432  // 105.7 KB -> 2 CTAs/SM

__global__ __launch_bounds__(NT, 2)
void country_attn_kernel(const float* __restrict__ infl,
                         const float* __restrict__ statf,
                         const float* __restrict__ Wc,
                         const float* __restrict__ bc,
                         const float* __restrict__ bqkv,
                         const float* __restrict__ ba,
                         const float* __restrict__ Wo,
                         const float* __restrict__ bo,
                         float* __restrict__ out)
{
    extern __shared__ float sm[];
    float* sWc   = sm + OFF_WC;
    float* sbc   = sm + OFF_BC;
    float* sbqkv = sm + OFF_BQKV;
    float* sba   = sm + OFF_BA;
    float* sStat = sm + OFF_STAT;
    float* sInf  = sm + OFF_INF;
    float* sRid  = sm + OFF_RID;
    float* sCnt  = sm + OFF_CNT;
    float* sTokT = sm + OFF_TOK;   // tokT[d][s], stride 88; later ctxT[d][q]
    float* sQKV  = sm + OFF_QKV;   // qkv[row][col], 88 x 192
    float* sCat  = sm + OFF_CAT;
    float* sPart = sm + OFF_PART;

    const int tid = threadIdx.x;
    const int b   = blockIdx.x;

    // ---- stage small weights / per-sample inputs ----
    {
        const float4* src = (const float4*)Wc; float4* dst = (float4*)sWc;
        for (int i = tid; i < 13*16; i += NT) dst[i] = src[i];
    }
    for (int i = tid; i < NS*NFEAT; i += NT) sStat[i] = statf[i];
    for (int i = tid; i < BINF; i += NT) sInf[i] = infl[(size_t)b * BINF + i];
    if (tid < 64)  { sbc[tid] = bc[tid]; sba[tid] = ba[tid]; }
    if (tid >= 64 && tid < 256) sbqkv[tid - 64] = bqkv[tid - 64];
    __syncthreads();

    // region id per token + counts
    if (tid < NS) {
        float r = 0.f;
        #pragma unroll
        for (int j = 0; j < NR; j++)
            if (sStat[tid*NFEAT + 2 + j] > 0.5f) r = (float)j;
        sRid[tid] = r;
    }
    if (tid >= 96 && tid < 96 + NR) {
        int rr = tid - 96;
        float c = 0.f;
        for (int s = 0; s < NS; s++)
            c += (sStat[s*NFEAT + 2 + rr] > 0.5f) ? 1.f : 0.f;
        sCnt[rr] = fmaxf(c, 1.f);
    }
    // zero pad cols s=86,87 of tokT
    if (tid >= 128 && tid < 256) {
        int t = tid - 128;
        sTokT[(t >> 1)*88 + 86 + (t & 1)] = 0.f;
    }

    // ---- phase 1: tokT[d][s] = relu(feats @ Wc + bc)^T ----
    for (int u = tid; u < NS*8; u += NT) {
        int d0 = (u / 86) * 8;
        int s  = u % 86;
        float f[13];
        f[0] = sInf[s] * 0.1f;
        f[1] = sInf[NS + s] * 0.1f;
        #pragma unroll
        for (int j = 0; j < NFEAT; j++) f[2 + j] = sStat[s*NFEAT + j];
        float4 b0 = *(const float4*)(sbc + d0);
        float4 b1 = *(const float4*)(sbc + d0 + 4);
        float acc[8] = {b0.x,b0.y,b0.z,b0.w, b1.x,b1.y,b1.z,b1.w};
        #pragma unroll
        for (int r = 0; r < 13; r++) {
            float4 w0 = *(const float4*)(sWc + r*64 + d0);
            float4 w1 = *(const float4*)(sWc + r*64 + d0 + 4);
            acc[0] = fmaf(f[r], w0.x, acc[0]); acc[1] = fmaf(f[r], w0.y, acc[1]);
            acc[2] = fmaf(f[r], w0.z, acc[2]); acc[3] = fmaf(f[r], w0.w, acc[3]);
            acc[4] = fmaf(f[r], w1.x, acc[4]); acc[5] = fmaf(f[r], w1.y, acc[5]);
            acc[6] = fmaf(f[r], w1.z, acc[6]); acc[7] = fmaf(f[r], w1.w, acc[7]);
        }
        #pragma unroll
        for (int j = 0; j < 8; j++)
            sTokT[(d0 + j)*88 + s] = fmaxf(acc[j], 0.f);
    }
    __syncthreads();

    // ---- phase 2: qkv = tokens @ Wqkv + bqkv, 8-row x 4-col tiles ----
    // 528 units; row-PAIR packing: token pairs free from LDS.128, weight
    // splats free from duplicated LDG.128 -> zero PACK movs in the loop.
    for (int u = tid; u < 528; u += NT) {
        int oct = u / 48;
        int n4  = (u % 48) * 4;
        ull acc[4][4];   // [row-pair][col]
        #pragma unroll
        for (int j = 0; j < 4; j++) {
            float bj = sbqkv[n4 + j];
            ull bs; PACK2(bs, bj, bj);
            acc[0][j] = bs; acc[1][j] = bs; acc[2][j] = bs; acc[3][j] = bs;
        }
        const float* tb0 = sTokT + oct*8;
        const float* wd  = g_Wd + n4*2;
        ulonglong2 w01 = __ldg((const ulonglong2*)(wd));
        ulonglong2 w23 = __ldg((const ulonglong2*)(wd + 4));
        ulonglong2 tA = *(const ulonglong2*)(tb0);
        ulonglong2 tB = *(const ulonglong2*)(tb0 + 4);
        #pragma unroll 4
        for (int k = 0; k < 64; k++) {
            ulonglong2 w01n, w23n, tAn, tBn;
            if (k < 63) {
                w01n = __ldg((const ulonglong2*)(wd + (k+1)*384));
                w23n = __ldg((const ulonglong2*)(wd + (k+1)*384 + 4));
                tAn = *(const ulonglong2*)(tb0 + (k+1)*88);
                tBn = *(const ulonglong2*)(tb0 + (k+1)*88 + 4);
            }
            ull tp[4] = {tA.x, tA.y, tB.x, tB.y};
            ull ws[4] = {w01.x, w01.y, w23.x, w23.y};
            #pragma unroll
            for (int i = 0; i < 4; i++) {
                FMA2(acc[i][0], tp[i], ws[0], acc[i][0]);
                FMA2(acc[i][1], tp[i], ws[1], acc[i][1]);
                FMA2(acc[i][2], tp[i], ws[2], acc[i][2]);
                FMA2(acc[i][3], tp[i], ws[3], acc[i][3]);
            }
            w01 = w01n; w23 = w23n; tA = tAn; tB = tBn;
        }
        #pragma unroll
        for (int i = 0; i < 4; i++) {
            float lo0,hi0,lo1,hi1,lo2,hi2,lo3,hi3;
            UNPACK2(lo0,hi0,acc[i][0]); UNPACK2(lo1,hi1,acc[i][1]);
            UNPACK2(lo2,hi2,acc[i][2]); UNPACK2(lo3,hi3,acc[i][3]);
            float* o0 = sQKV + (oct*8 + 2*i)*192 + n4;
            *(float4*)(o0)       = make_float4(lo0, lo1, lo2, lo3);
            *(float4*)(o0 + 192) = make_float4(hi0, hi1, hi2, hi3);
        }
    }
    __syncthreads();

    // ---- phase 3: attention (packed f32x2). unit = (query-pair, head): 172 ----
    if (tid < 172) {
        int h  = tid / 43;
        int qi = tid % 43;
        int q0 = qi*2, q1 = q0 + 1;

        ull quart; PACK2(quart, 0.25f, 0.25f);
        const ulonglong2* qp0 = (const ulonglong2*)(sQKV + q0*192 + h*HDIM);
        const ulonglong2* qp1 = (const ulonglong2*)(sQKV + q1*192 + h*HDIM);
        ull qv0[8], qv1[8];
        #pragma unroll
        for (int j = 0; j < 4; j++) {
            ulonglong2 a0 = qp0[j], a1 = qp1[j];
            MUL2(qv0[2*j],   a0.x, quart); MUL2(qv0[2*j+1], a0.y, quart);
            MUL2(qv1[2*j],   a1.x, quart); MUL2(qv1[2*j+1], a1.y, quart);
        }

        const float* kbase = sQKV + 64  + h*HDIM;
        const float* vbase = sQKV + 128 + h*HDIM;

        ull acc0[8], acc1[8];
        #pragma unroll
        for (int j = 0; j < 8; j++) { acc0[j] = 0ull; acc1[j] = 0ull; }
        float s0 = 0.f, s1 = 0.f;

        #pragma unroll 2
        for (int k = 0; k < NS; k++) {
            const ulonglong2* kp = (const ulonglong2*)(kbase + k*192);
            ull d20 = 0ull, d21 = 0ull;
            #pragma unroll
            for (int j = 0; j < 4; j++) {
                ulonglong2 kv = kp[j];
                FMA2(d20, qv0[2*j],   kv.x, d20);
                FMA2(d20, qv0[2*j+1], kv.y, d20);
                FMA2(d21, qv1[2*j],   kv.x, d21);
                FMA2(d21, qv1[2*j+1], kv.y, d21);
            }
            float lo0, hi0, lo1, hi1;
            UNPACK2(lo0, hi0, d20);
            UNPACK2(lo1, hi1, d21);
            float e0 = __expf(lo0 + hi0), e1 = __expf(lo1 + hi1);
            s0 += e0; s1 += e1;
            ull e20, e21;
            PACK2(e20, e0, e0); PACK2(e21, e1, e1);
            const ulonglong2* vp = (const ulonglong2*)(vbase + k*192);
            #pragma unroll
            for (int j = 0; j < 4; j++) {
                ulonglong2 vv = vp[j];
                FMA2(acc0[2*j],   e20, vv.x, acc0[2*j]);
                FMA2(acc0[2*j+1], e20, vv.y, acc0[2*j+1]);
                FMA2(acc1[2*j],   e21, vv.x, acc1[2*j]);
                FMA2(acc1[2*j+1], e21, vv.y, acc1[2*j+1]);
            }
        }
        float inv0 = 1.f / s0, inv1 = 1.f / s1;
        float* ct = sTokT + (h*HDIM)*88;
        #pragma unroll
        for (int j = 0; j < 8; j++) {
            float lo, hi;
            UNPACK2(lo, hi, acc0[j]);
            ct[(2*j)*88 + q0] = lo * inv0;
            ct[(2*j+1)*88 + q0] = hi * inv0;
            UNPACK2(lo, hi, acc1[j]);
            ct[(2*j)*88 + q1] = lo * inv1;
            ct[(2*j+1)*88 + q1] = hi * inv1;
        }
    }
    __syncthreads();

    // ---- phase 4: attn_out = ctx @ Wa + ba, 8x4 tiles, row-pair packed ----
    float* sAO = sQKV;
    if (tid < 176) {
        int oct = tid >> 4;
        int n4  = (tid & 15) * 4;
        ull acc[4][4];
        #pragma unroll
        for (int j = 0; j < 4; j++) {
            float bj = sba[n4 + j];
            ull bs; PACK2(bs, bj, bj);
            acc[0][j] = bs; acc[1][j] = bs; acc[2][j] = bs; acc[3][j] = bs;
        }
        const float* tb0 = sTokT + oct*8;
        const float* wd  = g_Wad + n4*2;
        ulonglong2 w01 = __ldg((const ulonglong2*)(wd));
        ulonglong2 w23 = __ldg((const ulonglong2*)(wd + 4));
        ulonglong2 tA = *(const ulonglong2*)(tb0);
        ulonglong2 tB = *(const ulonglong2*)(tb0 + 4);
        #pragma unroll 4
        for (int k = 0; k < 64; k++) {
            ulonglong2 w01n, w23n, tAn, tBn;
            if (k < 63) {
                w01n = __ldg((const ulonglong2*)(wd + (k+1)*128));
                w23n = __ldg((const ulonglong2*)(wd + (k+1)*128 + 4));
                tAn = *(const ulonglong2*)(tb0 + (k+1)*88);
                tBn = *(const ulonglong2*)(tb0 + (k+1)*88 + 4);
            }
            ull tp[4] = {tA.x, tA.y, tB.x, tB.y};
            ull ws[4] = {w01.x, w01.y, w23.x, w23.y};
            #pragma unroll
            for (int i = 0; i < 4; i++) {
                FMA2(acc[i][0], tp[i], ws[0], acc[i][0]);
                FMA2(acc[i][1], tp[i], ws[1], acc[i][1]);
                FMA2(acc[i][2], tp[i], ws[2], acc[i][2]);
                FMA2(acc[i][3], tp[i], ws[3], acc[i][3]);
            }
            w01 = w01n; w23 = w23n; tA = tAn; tB = tBn;
        }
        #pragma unroll
        for (int i = 0; i < 4; i++) {
            float lo0,hi0,lo1,hi1,lo2,hi2,lo3,hi3;
            UNPACK2(lo0,hi0,acc[i][0]); UNPACK2(lo1,hi1,acc[i][1]);
            UNPACK2(lo2,hi2,acc[i][2]); UNPACK2(lo3,hi3,acc[i][3]);
            float* o0 = sAO + (oct*8 + 2*i)*64 + n4;
            *(float4*)(o0)      = make_float4(lo0, lo1, lo2, lo3);
            *(float4*)(o0 + 64) = make_float4(hi0, hi1, hi2, hi3);
        }
    }
    __syncthreads();

    // ---- phase 5a: quartered pooling partials ----
    if (tid < 256) {
        int d  = tid & 63;
        int sq = tid >> 6;
        int s0 = sq * 22;
        int s1 = (sq == 3) ? NS : s0 + 22;
        float accg = 0.f, accr[NR];
        #pragma unroll
        for (int j = 0; j < NR; j++) accr[j] = 0.f;
        for (int s = s0; s < s1; s++) {
            float v = sAO[s*64 + d];
            int r = (int)sRid[s];
            accg += v;
            #pragma unroll
            for (int j = 0; j < NR; j++)
                accr[j] += (r == j) ? v : 0.f;
        }
        float* pp = sPart + (sq & 1)*512 + d;
        if (sq < 2) {
            pp[0] = accg;
            #pragma unroll
            for (int j = 0; j < NR; j++) pp[(1 + j)*64] = accr[j];
        }
        __syncthreads();
        if (sq >= 2) {
            atomicAdd(&pp[0], accg);
            #pragma unroll
            for (int j = 0; j < NR; j++) atomicAdd(&pp[(1 + j)*64], accr[j]);
        }
    }
    __syncthreads();

    // ---- phase 5b: finalize concat (512) ----
    for (int i = tid; i < 512; i += NT) {
        int g = i >> 6;
        float s = sPart[i] + sPart[512 + i];
        sCat[i] = (g == 0) ? s * (1.f / 86.f) : s / sCnt[g - 1];
    }
    __syncthreads();

    // ---- phase 6: out = relu(concat @ Wo + bo), float4 Wo loads (L2) ----
    {
        int ic = tid >> 5;          // 0..7 (warp id), i-chunk of 64
        int cg = tid & 31;          // col group, j = 4*cg
        const float4* wp = (const float4*)(Wo + (size_t)(ic*64)*128) + cg;
        float a0 = 0.f, a1 = 0.f, a2 = 0.f, a3 = 0.f;
        #pragma unroll 8
        for (int i = 0; i < 64; i++) {
            float c = sCat[ic*64 + i];
            float4 w = __ldg(wp + (size_t)i * 32);
            a0 = fmaf(c, w.x, a0); a1 = fmaf(c, w.y, a1);
            a2 = fmaf(c, w.z, a2); a3 = fmaf(c, w.w, a3);
        }
        *(float4*)(sPart + ic*128 + cg*4) = make_float4(a0, a1, a2, a3);
    }
    __syncthreads();
    if (tid < 128) {
        float acc = bo[tid];
        #pragma unroll
        for (int ic = 0; ic < 8; ic++) acc += sPart[ic*128 + tid];
        out[(size_t)b * 128 + tid] = fmaxf(acc, 0.f);
    }
}

extern "C" void kernel_launch(void* const* d_in, const int* in_sizes, int n_in,
                              void* d_out, int out_size)
{
    const float* infl  = (const float*)d_in[0];
    const float* statf = (const float*)d_in[1];
    const float* Wc    = (const float*)d_in[2];
    const float* bc    = (const float*)d_in[3];
    const float* Wqkv  = (const float*)d_in[4];
    const float* bqkv  = (const float*)d_in[5];
    const float* Wa    = (const float*)d_in[6];
    const float* ba    = (const float*)d_in[7];
    const float* Wo    = (const float*)d_in[8];
    const float* bo    = (const float*)d_in[9];
    float* out = (float*)d_out;

    int B = in_sizes[0] / BINF;
    prep_kernel<<<64, 256>>>(Wqkv, Wa);
    size_t smem = SMEM_FLOATS * sizeof(float);
    cudaFuncSetAttribute(country_attn_kernel,
                         cudaFuncAttributeMaxDynamicSharedMemorySize, (int)smem);
    country_attn_kernel<<<B, NT, smem>>>(infl, statf, Wc, bc, bqkv,
                                         ba, Wo, bo, out);
}

// round 14
// speedup vs baseline: 1.1239x; 1.1239x over previous
#include <cuda_runtime.h>

typedef unsigned long long ull;

#define FMA2(d, a, bb, c) \
    asm("fma.rn.f32x2 %0, %1, %2, %3;" : "=l"(d) : "l"(a), "l"(bb), "l"(c))
#define MUL2(d, a, bb) \
    asm("mul.rn.f32x2 %0, %1, %2;" : "=l"(d) : "l"(a), "l"(bb))
#define PACK2(d, lo, hi) \
    asm("mov.b64 %0, {%1, %2};" : "=l"(d) : "f"(lo), "f"(hi))
#define UNPACK2(lo, hi, s) \
    asm("mov.b64 {%0, %1}, %2;" : "=f"(lo), "=f"(hi) : "l"(s))

#define NS   86
#define DM   64
#define NH   4
#define HDIM 16
#define NFEAT 11
#define NR   7
#define NT   256
#define BINF (2*NS)

// smem float offsets (Wqkv / Wa streamed from L2, not staged)
#define OFF_WC    0        // 832
#define OFF_BC    832      // 64
#define OFF_BQKV  896      // 192
#define OFF_BA    1088     // 64
#define OFF_STAT  1152     // 948
#define OFF_INF   2100     // 172
#define OFF_RID   2272     // 88
#define OFF_CNT   2360     // 8
#define OFF_TOK   2368     // tokT / ctxT: 64*88 = 5632
#define OFF_QKV   8000     // 88*192 = 16896 (reused as attn_out)
#define OFF_CAT   24896    // 512
#define OFF_PART  25408    // 1024
#define SMEM_FLOATS 26432  // 105.7 KB -> 2 CTAs/SM

// 0.25f * log2(e): folds both the 1/sqrt(HDIM) scale and the exp->exp2
// conversion into the q pre-scale, so softmax exp is a bare MUFU.EX2.
#define QSCALE 0.3606737602222409f

__global__ __launch_bounds__(NT, 2)
void country_attn_kernel(const float* __restrict__ infl,
                         const float* __restrict__ statf,
                         const float* __restrict__ Wc,
                         const float* __restrict__ bc,
                         const float* __restrict__ Wqkv,
                         const float* __restrict__ bqkv,
                         const float* __restrict__ Wa,
                         const float* __restrict__ ba,
                         const float* __restrict__ Wo,
                         const float* __restrict__ bo,
                         float* __restrict__ out)
{
    extern __shared__ float sm[];
    float* sWc   = sm + OFF_WC;
    float* sbc   = sm + OFF_BC;
    float* sbqkv = sm + OFF_BQKV;
    float* sba   = sm + OFF_BA;
    float* sStat = sm + OFF_STAT;
    float* sInf  = sm + OFF_INF;
    float* sRid  = sm + OFF_RID;
    float* sCnt  = sm + OFF_CNT;
    float* sTokT = sm + OFF_TOK;   // tokT[d][s], stride 88; later ctxT[d][q]
    float* sQKV  = sm + OFF_QKV;   // qkv[row][col], 88 x 192
    float* sCat  = sm + OFF_CAT;
    float* sPart = sm + OFF_PART;

    const int tid = threadIdx.x;
    const int b   = blockIdx.x;

    // ---- stage small weights / per-sample inputs ----
    {
        const float4* src = (const float4*)Wc; float4* dst = (float4*)sWc;
        for (int i = tid; i < 13*16; i += NT) dst[i] = src[i];
    }
    for (int i = tid; i < NS*NFEAT; i += NT) sStat[i] = statf[i];
    for (int i = tid; i < BINF; i += NT) sInf[i] = infl[(size_t)b * BINF + i];
    if (tid < 64)  { sbc[tid] = bc[tid]; sba[tid] = ba[tid]; }
    if (tid >= 64 && tid < 256) sbqkv[tid - 64] = bqkv[tid - 64];
    __syncthreads();

    // region id per token + counts
    if (tid < NS) {
        float r = 0.f;
        #pragma unroll
        for (int j = 0; j < NR; j++)
            if (sStat[tid*NFEAT + 2 + j] > 0.5f) r = (float)j;
        sRid[tid] = r;
    }
    if (tid >= 96 && tid < 96 + NR) {
        int rr = tid - 96;
        float c = 0.f;
        for (int s = 0; s < NS; s++)
            c += (sStat[s*NFEAT + 2 + rr] > 0.5f) ? 1.f : 0.f;
        sCnt[rr] = fmaxf(c, 1.f);
    }
    // zero pad cols s=86,87 of tokT
    if (tid >= 128 && tid < 256) {
        int t = tid - 128;
        sTokT[(t >> 1)*88 + 86 + (t & 1)] = 0.f;
    }

    // ---- phase 1: tokT[d][s] = relu(feats @ Wc + bc)^T ----
    for (int u = tid; u < NS*8; u += NT) {
        int d0 = (u / 86) * 8;
        int s  = u % 86;
        float f[13];
        f[0] = sInf[s] * 0.1f;
        f[1] = sInf[NS + s] * 0.1f;
        #pragma unroll
        for (int j = 0; j < NFEAT; j++) f[2 + j] = sStat[s*NFEAT + j];
        float4 b0 = *(const float4*)(sbc + d0);
        float4 b1 = *(const float4*)(sbc + d0 + 4);
        float acc[8] = {b0.x,b0.y,b0.z,b0.w, b1.x,b1.y,b1.z,b1.w};
        #pragma unroll
        for (int r = 0; r < 13; r++) {
            float4 w0 = *(const float4*)(sWc + r*64 + d0);
            float4 w1 = *(const float4*)(sWc + r*64 + d0 + 4);
            acc[0] = fmaf(f[r], w0.x, acc[0]); acc[1] = fmaf(f[r], w0.y, acc[1]);
            acc[2] = fmaf(f[r], w0.z, acc[2]); acc[3] = fmaf(f[r], w0.w, acc[3]);
            acc[4] = fmaf(f[r], w1.x, acc[4]); acc[5] = fmaf(f[r], w1.y, acc[5]);
            acc[6] = fmaf(f[r], w1.z, acc[6]); acc[7] = fmaf(f[r], w1.w, acc[7]);
        }
        #pragma unroll
        for (int j = 0; j < 8; j++)
            sTokT[(d0 + j)*88 + s] = fmaxf(acc[j], 0.f);
    }
    __syncthreads();

    // ---- phase 2: qkv = tokens @ Wqkv + bqkv, 8-row x 4-col tiles ----
    // 528 units; weights from L2 with DEPTH-2 register prefetch.
    for (int u = tid; u < 528; u += NT) {
        int oct = u / 48;
        int n4  = (u % 48) * 4;
        ulonglong2 bb = *(const ulonglong2*)(sbqkv + n4);
        ull acc[8][2];
        #pragma unroll
        for (int r = 0; r < 8; r++) { acc[r][0] = bb.x; acc[r][1] = bb.y; }
        const float* tb0 = sTokT + oct*8;
        ulonglong2 w_cur = __ldg((const ulonglong2*)(Wqkv + n4));
        ulonglong2 w_nx  = __ldg((const ulonglong2*)(Wqkv + 192 + n4));
        float4 ta = *(const float4*)(tb0);
        float4 tc = *(const float4*)(tb0 + 4);
        #pragma unroll 4
        for (int k = 0; k < 64; k++) {
            ulonglong2 w_n2; float4 tna, tnc;
            if (k < 62)
                w_n2 = __ldg((const ulonglong2*)(Wqkv + (k+2)*192 + n4));
            if (k < 63) {
                tna = *(const float4*)(tb0 + (k+1)*88);
                tnc = *(const float4*)(tb0 + (k+1)*88 + 4);
            }
            ull tp[8];
            PACK2(tp[0], ta.x, ta.x); PACK2(tp[1], ta.y, ta.y);
            PACK2(tp[2], ta.z, ta.z); PACK2(tp[3], ta.w, ta.w);
            PACK2(tp[4], tc.x, tc.x); PACK2(tp[5], tc.y, tc.y);
            PACK2(tp[6], tc.z, tc.z); PACK2(tp[7], tc.w, tc.w);
            #pragma unroll
            for (int r = 0; r < 8; r++) {
                FMA2(acc[r][0], tp[r], w_cur.x, acc[r][0]);
                FMA2(acc[r][1], tp[r], w_cur.y, acc[r][1]);
            }
            w_cur = w_nx; w_nx = w_n2; ta = tna; tc = tnc;
        }
        #pragma unroll
        for (int r = 0; r < 8; r++)
            *(ulonglong2*)(sQKV + (oct*8 + r)*192 + n4) =
                make_ulonglong2(acc[r][0], acc[r][1]);
    }
    __syncthreads();

    // ---- phase 3: attention (packed f32x2). unit = (query-pair, head): 172 ----
    if (tid < 172) {
        int h  = tid / 43;
        int qi = tid % 43;
        int q0 = qi*2, q1 = q0 + 1;

        ull qsc; PACK2(qsc, QSCALE, QSCALE);
        const ulonglong2* qp0 = (const ulonglong2*)(sQKV + q0*192 + h*HDIM);
        const ulonglong2* qp1 = (const ulonglong2*)(sQKV + q1*192 + h*HDIM);
        ull qv0[8], qv1[8];
        #pragma unroll
        for (int j = 0; j < 4; j++) {
            ulonglong2 a0 = qp0[j], a1 = qp1[j];
            MUL2(qv0[2*j],   a0.x, qsc); MUL2(qv0[2*j+1], a0.y, qsc);
            MUL2(qv1[2*j],   a1.x, qsc); MUL2(qv1[2*j+1], a1.y, qsc);
        }

        const float* kbase = sQKV + 64  + h*HDIM;
        const float* vbase = sQKV + 128 + h*HDIM;

        ull acc0[8], acc1[8];
        #pragma unroll
        for (int j = 0; j < 8; j++) { acc0[j] = 0ull; acc1[j] = 0ull; }
        float s0 = 0.f, s1 = 0.f;

        #pragma unroll 2
        for (int k = 0; k < NS; k++) {
            const ulonglong2* kp = (const ulonglong2*)(kbase + k*192);
            ull d20 = 0ull, d21 = 0ull;
            #pragma unroll
            for (int j = 0; j < 4; j++) {
                ulonglong2 kv = kp[j];
                FMA2(d20, qv0[2*j],   kv.x, d20);
                FMA2(d20, qv0[2*j+1], kv.y, d20);
                FMA2(d21, qv1[2*j],   kv.x, d21);
                FMA2(d21, qv1[2*j+1], kv.y, d21);
            }
            float lo0, hi0, lo1, hi1;
            UNPACK2(lo0, hi0, d20);
            UNPACK2(lo1, hi1, d21);
            float e0 = exp2f(lo0 + hi0), e1 = exp2f(lo1 + hi1);
            s0 += e0; s1 += e1;
            ull e20, e21;
            PACK2(e20, e0, e0); PACK2(e21, e1, e1);
            const ulonglong2* vp = (const ulonglong2*)(vbase + k*192);
            #pragma unroll
            for (int j = 0; j < 4; j++) {
                ulonglong2 vv = vp[j];
                FMA2(acc0[2*j],   e20, vv.x, acc0[2*j]);
                FMA2(acc0[2*j+1], e20, vv.y, acc0[2*j+1]);
                FMA2(acc1[2*j],   e21, vv.x, acc1[2*j]);
                FMA2(acc1[2*j+1], e21, vv.y, acc1[2*j+1]);
            }
        }
        float inv0 = 1.f / s0, inv1 = 1.f / s1;
        float* ct = sTokT + (h*HDIM)*88;
        #pragma unroll
        for (int j = 0; j < 8; j++) {
            float lo, hi;
            UNPACK2(lo, hi, acc0[j]);
            ct[(2*j)*88 + q0] = lo * inv0;
            ct[(2*j+1)*88 + q0] = hi * inv0;
            UNPACK2(lo, hi, acc1[j]);
            ct[(2*j)*88 + q1] = lo * inv1;
            ct[(2*j+1)*88 + q1] = hi * inv1;
        }
    }
    __syncthreads();

    // ---- phase 4: attn_out = ctx @ Wa + ba, 8x4 tiles; Wa from L2,
    //      DEPTH-2 register prefetch ----
    float* sAO = sQKV;
    if (tid < 176) {
        int oct = tid >> 4;
        int n4  = (tid & 15) * 4;
        ulonglong2 bb = *(const ulonglong2*)(sba + n4);
        ull acc[8][2];
        #pragma unroll
        for (int r = 0; r < 8; r++) { acc[r][0] = bb.x; acc[r][1] = bb.y; }
        const float* tb0 = sTokT + oct*8;
        ulonglong2 w_cur = __ldg((const ulonglong2*)(Wa + n4));
        ulonglong2 w_nx  = __ldg((const ulonglong2*)(Wa + 64 + n4));
        float4 ta = *(const float4*)(tb0);
        float4 tc = *(const float4*)(tb0 + 4);
        #pragma unroll 4
        for (int k = 0; k < 64; k++) {
            ulonglong2 w_n2; float4 tna, tnc;
            if (k < 62)
                w_n2 = __ldg((const ulonglong2*)(Wa + (k+2)*64 + n4));
            if (k < 63) {
                tna = *(const float4*)(tb0 + (k+1)*88);
                tnc = *(const float4*)(tb0 + (k+1)*88 + 4);
            }
            ull tp[8];
            PACK2(tp[0], ta.x, ta.x); PACK2(tp[1], ta.y, ta.y);
            PACK2(tp[2], ta.z, ta.z); PACK2(tp[3], ta.w, ta.w);
            PACK2(tp[4], tc.x, tc.x); PACK2(tp[5], tc.y, tc.y);
            PACK2(tp[6], tc.z, tc.z); PACK2(tp[7], tc.w, tc.w);
            #pragma unroll
            for (int r = 0; r < 8; r++) {
                FMA2(acc[r][0], tp[r], w_cur.x, acc[r][0]);
                FMA2(acc[r][1], tp[r], w_cur.y, acc[r][1]);
            }
            w_cur = w_nx; w_nx = w_n2; ta = tna; tc = tnc;
        }
        #pragma unroll
        for (int r = 0; r < 8; r++)
            *(ulonglong2*)(sAO + (oct*8 + r)*64 + n4) =
                make_ulonglong2(acc[r][0], acc[r][1]);
    }
    __syncthreads();

    // ---- phase 5a: quartered pooling partials ----
    if (tid < 256) {
        int d  = tid & 63;
        int sq = tid >> 6;
        int s0 = sq * 22;
        int s1 = (sq == 3) ? NS : s0 + 22;
        float accg = 0.f, accr[NR];
        #pragma unroll
        for (int j = 0; j < NR; j++) accr[j] = 0.f;
        for (int s = s0; s < s1; s++) {
            float v = sAO[s*64 + d];
            int r = (int)sRid[s];
            accg += v;
            #pragma unroll
            for (int j = 0; j < NR; j++)
                accr[j] += (r == j) ? v : 0.f;
        }
        float* pp = sPart + (sq & 1)*512 + d;
        if (sq < 2) {
            pp[0] = accg;
            #pragma unroll
            for (int j = 0; j < NR; j++) pp[(1 + j)*64] = accr[j];
        }
        __syncthreads();
        if (sq >= 2) {
            atomicAdd(&pp[0], accg);
            #pragma unroll
            for (int j = 0; j < NR; j++) atomicAdd(&pp[(1 + j)*64], accr[j]);
        }
    }
    __syncthreads();

    // ---- phase 5b: finalize concat (512) ----
    for (int i = tid; i < 512; i += NT) {
        int g = i >> 6;
        float s = sPart[i] + sPart[512 + i];
        sCat[i] = (g == 0) ? s * (1.f / 86.f) : s / sCnt[g - 1];
    }
    __syncthreads();

    // ---- phase 6: out = relu(concat @ Wo + bo), float4 Wo loads (L2) ----
    {
        int ic = tid >> 5;          // 0..7 (warp id), i-chunk of 64
        int cg = tid & 31;          // col group, j = 4*cg
        const float4* wp = (const float4*)(Wo + (size_t)(ic*64)*128) + cg;
        float a0 = 0.f, a1 = 0.f, a2 = 0.f, a3 = 0.f;
        #pragma unroll 8
        for (int i = 0; i < 64; i++) {
            float c = sCat[ic*64 + i];
            float4 w = __ldg(wp + (size_t)i * 32);
            a0 = fmaf(c, w.x, a0); a1 = fmaf(c, w.y, a1);
            a2 = fmaf(c, w.z, a2); a3 = fmaf(c, w.w, a3);
        }
        *(float4*)(sPart + ic*128 + cg*4) = make_float4(a0, a1, a2, a3);
    }
    __syncthreads();
    if (tid < 128) {
        float acc = bo[tid];
        #pragma unroll
        for (int ic = 0; ic < 8; ic++) acc += sPart[ic*128 + tid];
        out[(size_t)b * 128 + tid] = fmaxf(acc, 0.f);
    }
}

extern "C" void kernel_launch(void* const* d_in, const int* in_sizes, int n_in,
                              void* d_out, int out_size)
{
    const float* infl  = (const float*)d_in[0];
    const float* statf = (const float*)d_in[1];
    const float* Wc    = (const float*)d_in[2];
    const float* bc    = (const float*)d_in[3];
    const float* Wqkv  = (const float*)d_in[4];
    const float* bqkv  = (const float*)d_in[5];
    const float* Wa    = (const float*)d_in[6];
    const float* ba    = (const float*)d_in[7];
    const float* Wo    = (const float*)d_in[8];
    const float* bo    = (const float*)d_in[9];
    float* out = (float*)d_out;

    int B = in_sizes[0] / BINF;
    size_t smem = SMEM_FLOATS * sizeof(float);
    cudaFuncSetAttribute(country_attn_kernel,
                         cudaFuncAttributeMaxDynamicSharedMemorySize, (int)smem);
    country_attn_kernel<<<B, NT, smem>>>(infl, statf, Wc, bc, Wqkv, bqkv,
                                         Wa, ba, Wo, bo, out);
}

// round 15
// speedup vs baseline: 1.1740x; 1.0446x over previous
#include <cuda_runtime.h>

typedef unsigned long long ull;

#define FMA2(d, a, bb, c) \
    asm("fma.rn.f32x2 %0, %1, %2, %3;" : "=l"(d) : "l"(a), "l"(bb), "l"(c))
#define MUL2(d, a, bb) \
    asm("mul.rn.f32x2 %0, %1, %2;" : "=l"(d) : "l"(a), "l"(bb))
#define PACK2(d, lo, hi) \
    asm("mov.b64 %0, {%1, %2};" : "=l"(d) : "f"(lo), "f"(hi))
#define UNPACK2(lo, hi, s) \
    asm("mov.b64 {%0, %1}, %2;" : "=f"(lo), "=f"(hi) : "l"(s))

#define NS   86
#define DM   64
#define NH   4
#define HDIM 16
#define NFEAT 11
#define NR   7
#define NT   256
#define BINF (2*NS)

// smem float offsets (Wqkv / Wa streamed from L2, not staged)
#define OFF_WC    0        // 832
#define OFF_BC    832      // 64
#define OFF_BQKV  896      // 192
#define OFF_BA    1088     // 64
#define OFF_STAT  1152     // 948
#define OFF_INF   2100     // 172
#define OFF_RID   2272     // 88
#define OFF_CNT   2360     // 8
#define OFF_TOK   2368     // tokT / ctxT: 64*88 = 5632
#define OFF_QKV   8000     // 88*192 = 16896 (reused as attn_out)
#define OFF_CAT   24896    // 512
#define OFF_PART  25408    // 1024
#define SMEM_FLOATS 26432  // 105.7 KB -> 2 CTAs/SM

// 0.25f * log2(e): folds the 1/sqrt(HDIM) scale and the exp->exp2
// conversion into the q pre-scale, so softmax exp is a bare MUFU.EX2.
#define QSCALE 0.3606737602222409f

__global__ __launch_bounds__(NT, 2)
void country_attn_kernel(const float* __restrict__ infl,
                         const float* __restrict__ statf,
                         const float* __restrict__ Wc,
                         const float* __restrict__ bc,
                         const float* __restrict__ Wqkv,
                         const float* __restrict__ bqkv,
                         const float* __restrict__ Wa,
                         const float* __restrict__ ba,
                         const float* __restrict__ Wo,
                         const float* __restrict__ bo,
                         float* __restrict__ out)
{
    extern __shared__ float sm[];
    float* sWc   = sm + OFF_WC;
    float* sbc   = sm + OFF_BC;
    float* sbqkv = sm + OFF_BQKV;
    float* sba   = sm + OFF_BA;
    float* sStat = sm + OFF_STAT;
    float* sInf  = sm + OFF_INF;
    float* sRid  = sm + OFF_RID;
    float* sCnt  = sm + OFF_CNT;
    float* sTokT = sm + OFF_TOK;   // tokT[d][s], stride 88; later ctxT[d][q]
    float* sQKV  = sm + OFF_QKV;   // qkv[row][col], 88 x 192
    float* sCat  = sm + OFF_CAT;
    float* sPart = sm + OFF_PART;

    const int tid = threadIdx.x;
    const int b   = blockIdx.x;

    // ---- stage small weights / per-sample inputs ----
    {
        const float4* src = (const float4*)Wc; float4* dst = (float4*)sWc;
        for (int i = tid; i < 13*16; i += NT) dst[i] = src[i];
    }
    for (int i = tid; i < NS*NFEAT; i += NT) sStat[i] = statf[i];
    for (int i = tid; i < BINF; i += NT) sInf[i] = infl[(size_t)b * BINF + i];
    if (tid < 64)  { sbc[tid] = bc[tid]; sba[tid] = ba[tid]; }
    if (tid >= 64 && tid < 256) sbqkv[tid - 64] = bqkv[tid - 64];
    __syncthreads();

    // region id per token + counts
    if (tid < NS) {
        float r = 0.f;
        #pragma unroll
        for (int j = 0; j < NR; j++)
            if (sStat[tid*NFEAT + 2 + j] > 0.5f) r = (float)j;
        sRid[tid] = r;
    }
    if (tid >= 96 && tid < 96 + NR) {
        int rr = tid - 96;
        float c = 0.f;
        for (int s = 0; s < NS; s++)
            c += (sStat[s*NFEAT + 2 + rr] > 0.5f) ? 1.f : 0.f;
        sCnt[rr] = fmaxf(c, 1.f);
    }
    // zero pad cols s=86,87 of tokT
    if (tid >= 128 && tid < 256) {
        int t = tid - 128;
        sTokT[(t >> 1)*88 + 86 + (t & 1)] = 0.f;
    }

    // ---- phase 1: tokT[d][s] = relu(feats @ Wc + bc)^T ----
    for (int u = tid; u < NS*8; u += NT) {
        int d0 = (u / 86) * 8;
        int s  = u % 86;
        float f[13];
        f[0] = sInf[s] * 0.1f;
        f[1] = sInf[NS + s] * 0.1f;
        #pragma unroll
        for (int j = 0; j < NFEAT; j++) f[2 + j] = sStat[s*NFEAT + j];
        float4 b0 = *(const float4*)(sbc + d0);
        float4 b1 = *(const float4*)(sbc + d0 + 4);
        float acc[8] = {b0.x,b0.y,b0.z,b0.w, b1.x,b1.y,b1.z,b1.w};
        #pragma unroll
        for (int r = 0; r < 13; r++) {
            float4 w0 = *(const float4*)(sWc + r*64 + d0);
            float4 w1 = *(const float4*)(sWc + r*64 + d0 + 4);
            acc[0] = fmaf(f[r], w0.x, acc[0]); acc[1] = fmaf(f[r], w0.y, acc[1]);
            acc[2] = fmaf(f[r], w0.z, acc[2]); acc[3] = fmaf(f[r], w0.w, acc[3]);
            acc[4] = fmaf(f[r], w1.x, acc[4]); acc[5] = fmaf(f[r], w1.y, acc[5]);
            acc[6] = fmaf(f[r], w1.z, acc[6]); acc[7] = fmaf(f[r], w1.w, acc[7]);
        }
        #pragma unroll
        for (int j = 0; j < 8; j++)
            sTokT[(d0 + j)*88 + s] = fmaxf(acc[j], 0.f);
    }
    __syncthreads();

    // ---- phase 2: qkv = tokens @ Wqkv + bqkv, 8-row x 4-col tiles ----
    // 11 octs x 48 col-groups = 528 units; weights from L2, double-buffered.
    for (int u = tid; u < 528; u += NT) {
        int oct = u / 48;
        int n4  = (u % 48) * 4;
        ulonglong2 bb = *(const ulonglong2*)(sbqkv + n4);
        ull acc[8][2];
        #pragma unroll
        for (int r = 0; r < 8; r++) { acc[r][0] = bb.x; acc[r][1] = bb.y; }
        const float* tb0 = sTokT + oct*8;
        ulonglong2 wc_ = __ldg((const ulonglong2*)(Wqkv + n4));
        float4 ta = *(const float4*)(tb0);
        float4 tc = *(const float4*)(tb0 + 4);
        #pragma unroll 4
        for (int k = 0; k < 64; k++) {
            ulonglong2 wn; float4 tna, tnc;
            if (k < 63) {
                wn  = __ldg((const ulonglong2*)(Wqkv + (k+1)*192 + n4));
                tna = *(const float4*)(tb0 + (k+1)*88);
                tnc = *(const float4*)(tb0 + (k+1)*88 + 4);
            }
            ull tp[8];
            PACK2(tp[0], ta.x, ta.x); PACK2(tp[1], ta.y, ta.y);
            PACK2(tp[2], ta.z, ta.z); PACK2(tp[3], ta.w, ta.w);
            PACK2(tp[4], tc.x, tc.x); PACK2(tp[5], tc.y, tc.y);
            PACK2(tp[6], tc.z, tc.z); PACK2(tp[7], tc.w, tc.w);
            #pragma unroll
            for (int r = 0; r < 8; r++) {
                FMA2(acc[r][0], tp[r], wc_.x, acc[r][0]);
                FMA2(acc[r][1], tp[r], wc_.y, acc[r][1]);
            }
            wc_ = wn; ta = tna; tc = tnc;
        }
        #pragma unroll
        for (int r = 0; r < 8; r++)
            *(ulonglong2*)(sQKV + (oct*8 + r)*192 + n4) =
                make_ulonglong2(acc[r][0], acc[r][1]);
    }
    __syncthreads();

    // ---- phase 3: attention (packed f32x2). unit = (query-pair, head): 172 ----
    if (tid < 172) {
        int h  = tid / 43;
        int qi = tid % 43;
        int q0 = qi*2, q1 = q0 + 1;

        ull qsc; PACK2(qsc, QSCALE, QSCALE);
        const ulonglong2* qp0 = (const ulonglong2*)(sQKV + q0*192 + h*HDIM);
        const ulonglong2* qp1 = (const ulonglong2*)(sQKV + q1*192 + h*HDIM);
        ull qv0[8], qv1[8];
        #pragma unroll
        for (int j = 0; j < 4; j++) {
            ulonglong2 a0 = qp0[j], a1 = qp1[j];
            MUL2(qv0[2*j],   a0.x, qsc); MUL2(qv0[2*j+1], a0.y, qsc);
            MUL2(qv1[2*j],   a1.x, qsc); MUL2(qv1[2*j+1], a1.y, qsc);
        }

        const float* kbase = sQKV + 64  + h*HDIM;
        const float* vbase = sQKV + 128 + h*HDIM;

        ull acc0[8], acc1[8];
        #pragma unroll
        for (int j = 0; j < 8; j++) { acc0[j] = 0ull; acc1[j] = 0ull; }
        float s0 = 0.f, s1 = 0.f;

        #pragma unroll 2
        for (int k = 0; k < NS; k++) {
            const ulonglong2* kp = (const ulonglong2*)(kbase + k*192);
            ull d20 = 0ull, d21 = 0ull;
            #pragma unroll
            for (int j = 0; j < 4; j++) {
                ulonglong2 kv = kp[j];
                FMA2(d20, qv0[2*j],   kv.x, d20);
                FMA2(d20, qv0[2*j+1], kv.y, d20);
                FMA2(d21, qv1[2*j],   kv.x, d21);
                FMA2(d21, qv1[2*j+1], kv.y, d21);
            }
            float lo0, hi0, lo1, hi1;
            UNPACK2(lo0, hi0, d20);
            UNPACK2(lo1, hi1, d21);
            float e0 = exp2f(lo0 + hi0), e1 = exp2f(lo1 + hi1);
            s0 += e0; s1 += e1;
            ull e20, e21;
            PACK2(e20, e0, e0); PACK2(e21, e1, e1);
            const ulonglong2* vp = (const ulonglong2*)(vbase + k*192);
            #pragma unroll
            for (int j = 0; j < 4; j++) {
                ulonglong2 vv = vp[j];
                FMA2(acc0[2*j],   e20, vv.x, acc0[2*j]);
                FMA2(acc0[2*j+1], e20, vv.y, acc0[2*j+1]);
                FMA2(acc1[2*j],   e21, vv.x, acc1[2*j]);
                FMA2(acc1[2*j+1], e21, vv.y, acc1[2*j+1]);
            }
        }
        float inv0 = 1.f / s0, inv1 = 1.f / s1;
        float* ct = sTokT + (h*HDIM)*88;
        #pragma unroll
        for (int j = 0; j < 8; j++) {
            float lo, hi;
            UNPACK2(lo, hi, acc0[j]);
            ct[(2*j)*88 + q0] = lo * inv0;
            ct[(2*j+1)*88 + q0] = hi * inv0;
            UNPACK2(lo, hi, acc1[j]);
            ct[(2*j)*88 + q1] = lo * inv1;
            ct[(2*j+1)*88 + q1] = hi * inv1;
        }
    }
    __syncthreads();

    // ---- phase 4: attn_out = ctx @ Wa + ba, 8x4 tiles; Wa from L2 ----
    float* sAO = sQKV;
    if (tid < 176) {
        int oct = tid >> 4;
        int n4  = (tid & 15) * 4;
        ulonglong2 bb = *(const ulonglong2*)(sba + n4);
        ull acc[8][2];
        #pragma unroll
        for (int r = 0; r < 8; r++) { acc[r][0] = bb.x; acc[r][1] = bb.y; }
        const float* tb0 = sTokT + oct*8;
        ulonglong2 wc_ = __ldg((const ulonglong2*)(Wa + n4));
        float4 ta = *(const float4*)(tb0);
        float4 tc = *(const float4*)(tb0 + 4);
        #pragma unroll 4
        for (int k = 0; k < 64; k++) {
            ulonglong2 wn; float4 tna, tnc;
            if (k < 63) {
                wn  = __ldg((const ulonglong2*)(Wa + (k+1)*64 + n4));
                tna = *(const float4*)(tb0 + (k+1)*88);
                tnc = *(const float4*)(tb0 + (k+1)*88 + 4);
            }
            ull tp[8];
            PACK2(tp[0], ta.x, ta.x); PACK2(tp[1], ta.y, ta.y);
            PACK2(tp[2], ta.z, ta.z); PACK2(tp[3], ta.w, ta.w);
            PACK2(tp[4], tc.x, tc.x); PACK2(tp[5], tc.y, tc.y);
            PACK2(tp[6], tc.z, tc.z); PACK2(tp[7], tc.w, tc.w);
            #pragma unroll
            for (int r = 0; r < 8; r++) {
                FMA2(acc[r][0], tp[r], wc_.x, acc[r][0]);
                FMA2(acc[r][1], tp[r], wc_.y, acc[r][1]);
            }
            wc_ = wn; ta = tna; tc = tnc;
        }
        #pragma unroll
        for (int r = 0; r < 8; r++)
            *(ulonglong2*)(sAO + (oct*8 + r)*64 + n4) =
                make_ulonglong2(acc[r][0], acc[r][1]);
    }
    __syncthreads();

    // ---- phase 5a: quartered pooling partials ----
    if (tid < 256) {
        int d  = tid & 63;
        int sq = tid >> 6;
        int s0 = sq * 22;
        int s1 = (sq == 3) ? NS : s0 + 22;
        float accg = 0.f, accr[NR];
        #pragma unroll
        for (int j = 0; j < NR; j++) accr[j] = 0.f;
        for (int s = s0; s < s1; s++) {
            float v = sAO[s*64 + d];
            int r = (int)sRid[s];
            accg += v;
            #pragma unroll
            for (int j = 0; j < NR; j++)
                accr[j] += (r == j) ? v : 0.f;
        }
        float* pp = sPart + (sq & 1)*512 + d;
        if (sq < 2) {
            pp[0] = accg;
            #pragma unroll
            for (int j = 0; j < NR; j++) pp[(1 + j)*64] = accr[j];
        }
        __syncthreads();
        if (sq >= 2) {
            atomicAdd(&pp[0], accg);
            #pragma unroll
            for (int j = 0; j < NR; j++) atomicAdd(&pp[(1 + j)*64], accr[j]);
        }
    }
    __syncthreads();

    // ---- phase 5b: finalize concat (512) ----
    for (int i = tid; i < 512; i += NT) {
        int g = i >> 6;
        float s = sPart[i] + sPart[512 + i];
        sCat[i] = (g == 0) ? s * (1.f / 86.f) : s / sCnt[g - 1];
    }
    __syncthreads();

    // ---- phase 6: out = relu(concat @ Wo + bo), float4 Wo loads (L2) ----
    {
        int ic = tid >> 5;          // 0..7 (warp id), i-chunk of 64
        int cg = tid & 31;          // col group, j = 4*cg
        const float4* wp = (const float4*)(Wo + (size_t)(ic*64)*128) + cg;
        float a0 = 0.f, a1 = 0.f, a2 = 0.f, a3 = 0.f;
        #pragma unroll 8
        for (int i = 0; i < 64; i++) {
            float c = sCat[ic*64 + i];
            float4 w = __ldg(wp + (size_t)i * 32);
            a0 = fmaf(c, w.x, a0); a1 = fmaf(c, w.y, a1);
            a2 = fmaf(c, w.z, a2); a3 = fmaf(c, w.w, a3);
        }
        *(float4*)(sPart + ic*128 + cg*4) = make_float4(a0, a1, a2, a3);
    }
    __syncthreads();
    if (tid < 128) {
        float acc = bo[tid];
        #pragma unroll
        for (int ic = 0; ic < 8; ic++) acc += sPart[ic*128 + tid];
        out[(size_t)b * 128 + tid] = fmaxf(acc, 0.f);
    }
}

extern "C" void kernel_launch(void* const* d_in, const int* in_sizes, int n_in,
                              void* d_out, int out_size)
{
    const float* infl  = (const float*)d_in[0];
    const float* statf = (const float*)d_in[1];
    const float* Wc    = (const float*)d_in[2];
    const float* bc    = (const float*)d_in[3];
    const float* Wqkv  = (const float*)d_in[4];
    const float* bqkv  = (const float*)d_in[5];
    const float* Wa    = (const float*)d_in[6];
    const float* ba    = (const float*)d_in[7];
    const float* Wo    = (const float*)d_in[8];
    const float* bo    = (const float*)d_in[9];
    float* out = (float*)d_out;

    int B = in_sizes[0] / BINF;
    size_t smem = SMEM_FLOATS * sizeof(float);
    cudaFuncSetAttribute(country_attn_kernel,
                         cudaFuncAttributeMaxDynamicSharedMemorySize, (int)smem);
    country_attn_kernel<<<B, NT, smem>>>(infl, statf, Wc, bc, Wqkv, bqkv,
                                         Wa, ba, Wo, bo, out);
}

// round 16
// speedup vs baseline: 1.2406x; 1.0567x over previous
#include <cuda_runtime.h>

typedef unsigned long long ull;

#define FMA2(d, a, bb, c) \
    asm("fma.rn.f32x2 %0, %1, %2, %3;" : "=l"(d) : "l"(a), "l"(bb), "l"(c))
#define MUL2(d, a, bb) \
    asm("mul.rn.f32x2 %0, %1, %2;" : "=l"(d) : "l"(a), "l"(bb))
#define PACK2(d, lo, hi) \
    asm("mov.b64 %0, {%1, %2};" : "=l"(d) : "f"(lo), "f"(hi))
#define UNPACK2(lo, hi, s) \
    asm("mov.b64 {%0, %1}, %2;" : "=f"(lo), "=f"(hi) : "l"(s))

#define NS   86
#define DM   64
#define NH   4
#define HDIM 16
#define NFEAT 11
#define NR   7
#define NT   384
#define BINF (2*NS)

// smem float offsets (Wqkv / Wa streamed from L2, not staged)
#define OFF_WC    0        // 832
#define OFF_BC    832      // 64
#define OFF_BQKV  896      // 192
#define OFF_BA    1088     // 64
#define OFF_STAT  1152     // 948
#define OFF_INF   2100     // 172
#define OFF_RID   2272     // 88
#define OFF_CNT   2360     // 8
#define OFF_TOK   2368     // tokT / ctxT: 64*88 = 5632
#define OFF_QKV   8000     // 88*192 = 16896 (reused as attn_out)
#define OFF_CAT   24896    // 512
#define OFF_PART  25408    // 1024
#define SMEM_FLOATS 26432  // 105.7 KB -> 2 CTAs/SM (24 warps)

// 0.25f * log2(e): folds the 1/sqrt(HDIM) scale and the exp->exp2
// conversion into the q pre-scale, so softmax exp is a bare MUFU.EX2.
#define QSCALE 0.3606737602222409f

__global__ __launch_bounds__(NT, 2)
void country_attn_kernel(const float* __restrict__ infl,
                         const float* __restrict__ statf,
                         const float* __restrict__ Wc,
                         const float* __restrict__ bc,
                         const float* __restrict__ Wqkv,
                         const float* __restrict__ bqkv,
                         const float* __restrict__ Wa,
                         const float* __restrict__ ba,
                         const float* __restrict__ Wo,
                         const float* __restrict__ bo,
                         float* __restrict__ out)
{
    extern __shared__ float sm[];
    float* sWc   = sm + OFF_WC;
    float* sbc   = sm + OFF_BC;
    float* sbqkv = sm + OFF_BQKV;
    float* sba   = sm + OFF_BA;
    float* sStat = sm + OFF_STAT;
    float* sInf  = sm + OFF_INF;
    float* sRid  = sm + OFF_RID;
    float* sCnt  = sm + OFF_CNT;
    float* sTokT = sm + OFF_TOK;   // tokT[d][s], stride 88; later ctxT[d][q]
    float* sQKV  = sm + OFF_QKV;   // qkv[row][col], 88 x 192
    float* sCat  = sm + OFF_CAT;
    float* sPart = sm + OFF_PART;

    const int tid = threadIdx.x;
    const int b   = blockIdx.x;

    // ---- stage small weights / per-sample inputs ----
    {
        const float4* src = (const float4*)Wc; float4* dst = (float4*)sWc;
        for (int i = tid; i < 13*16; i += NT) dst[i] = src[i];
    }
    for (int i = tid; i < NS*NFEAT; i += NT) sStat[i] = statf[i];
    for (int i = tid; i < BINF; i += NT) sInf[i] = infl[(size_t)b * BINF + i];
    if (tid < 64)  { sbc[tid] = bc[tid]; sba[tid] = ba[tid]; }
    if (tid >= 64 && tid < 256) sbqkv[tid - 64] = bqkv[tid - 64];
    __syncthreads();

    // region id per token + counts
    if (tid < NS) {
        float r = 0.f;
        #pragma unroll
        for (int j = 0; j < NR; j++)
            if (sStat[tid*NFEAT + 2 + j] > 0.5f) r = (float)j;
        sRid[tid] = r;
    }
    if (tid >= 96 && tid < 96 + NR) {
        int rr = tid - 96;
        float c = 0.f;
        for (int s = 0; s < NS; s++)
            c += (sStat[s*NFEAT + 2 + rr] > 0.5f) ? 1.f : 0.f;
        sCnt[rr] = fmaxf(c, 1.f);
    }
    // zero pad cols s=86,87 of tokT
    if (tid >= 128 && tid < 256) {
        int t = tid - 128;
        sTokT[(t >> 1)*88 + 86 + (t & 1)] = 0.f;
    }

    // ---- phase 1: tokT[d][s] = relu(feats @ Wc + bc)^T ----
    for (int u = tid; u < NS*8; u += NT) {
        int d0 = (u / 86) * 8;
        int s  = u % 86;
        float f[13];
        f[0] = sInf[s] * 0.1f;
        f[1] = sInf[NS + s] * 0.1f;
        #pragma unroll
        for (int j = 0; j < NFEAT; j++) f[2 + j] = sStat[s*NFEAT + j];
        float4 b0 = *(const float4*)(sbc + d0);
        float4 b1 = *(const float4*)(sbc + d0 + 4);
        float acc[8] = {b0.x,b0.y,b0.z,b0.w, b1.x,b1.y,b1.z,b1.w};
        #pragma unroll
        for (int r = 0; r < 13; r++) {
            float4 w0 = *(const float4*)(sWc + r*64 + d0);
            float4 w1 = *(const float4*)(sWc + r*64 + d0 + 4);
            acc[0] = fmaf(f[r], w0.x, acc[0]); acc[1] = fmaf(f[r], w0.y, acc[1]);
            acc[2] = fmaf(f[r], w0.z, acc[2]); acc[3] = fmaf(f[r], w0.w, acc[3]);
            acc[4] = fmaf(f[r], w1.x, acc[4]); acc[5] = fmaf(f[r], w1.y, acc[5]);
            acc[6] = fmaf(f[r], w1.z, acc[6]); acc[7] = fmaf(f[r], w1.w, acc[7]);
        }
        #pragma unroll
        for (int j = 0; j < 8; j++)
            sTokT[(d0 + j)*88 + s] = fmaxf(acc[j], 0.f);
    }
    __syncthreads();

    // ---- phase 2: qkv = tokens @ Wqkv + bqkv, 8-row x 4-col tiles ----
    // 11 octs x 48 col-groups = 528 units; weights from L2, double-buffered.
    for (int u = tid; u < 528; u += NT) {
        int oct = u / 48;
        int n4  = (u % 48) * 4;
        ulonglong2 bb = *(const ulonglong2*)(sbqkv + n4);
        ull acc[8][2];
        #pragma unroll
        for (int r = 0; r < 8; r++) { acc[r][0] = bb.x; acc[r][1] = bb.y; }
        const float* tb0 = sTokT + oct*8;
        ulonglong2 wc_ = __ldg((const ulonglong2*)(Wqkv + n4));
        float4 ta = *(const float4*)(tb0);
        float4 tc = *(const float4*)(tb0 + 4);
        #pragma unroll 4
        for (int k = 0; k < 64; k++) {
            ulonglong2 wn; float4 tna, tnc;
            if (k < 63) {
                wn  = __ldg((const ulonglong2*)(Wqkv + (k+1)*192 + n4));
                tna = *(const float4*)(tb0 + (k+1)*88);
                tnc = *(const float4*)(tb0 + (k+1)*88 + 4);
            }
            ull tp[8];
            PACK2(tp[0], ta.x, ta.x); PACK2(tp[1], ta.y, ta.y);
            PACK2(tp[2], ta.z, ta.z); PACK2(tp[3], ta.w, ta.w);
            PACK2(tp[4], tc.x, tc.x); PACK2(tp[5], tc.y, tc.y);
            PACK2(tp[6], tc.z, tc.z); PACK2(tp[7], tc.w, tc.w);
            #pragma unroll
            for (int r = 0; r < 8; r++) {
                FMA2(acc[r][0], tp[r], wc_.x, acc[r][0]);
                FMA2(acc[r][1], tp[r], wc_.y, acc[r][1]);
            }
            wc_ = wn; ta = tna; tc = tnc;
        }
        #pragma unroll
        for (int r = 0; r < 8; r++)
            *(ulonglong2*)(sQKV + (oct*8 + r)*192 + n4) =
                make_ulonglong2(acc[r][0], acc[r][1]);
    }
    __syncthreads();

    // ---- phase 3: attention (packed f32x2). unit = (head, query): 344 units,
    //      ONE pass at 384 threads; h-major so warps share K/V rows (broadcast).
    if (tid < 344) {
        int h = tid / 86;
        int q = tid - h*86;

        ull qsc; PACK2(qsc, QSCALE, QSCALE);
        const ulonglong2* qp = (const ulonglong2*)(sQKV + q*192 + h*HDIM);
        ull qv[8];
        #pragma unroll
        for (int j = 0; j < 4; j++) {
            ulonglong2 a0 = qp[j];
            MUL2(qv[2*j],   a0.x, qsc);
            MUL2(qv[2*j+1], a0.y, qsc);
        }

        const float* kbase = sQKV + 64  + h*HDIM;
        const float* vbase = sQKV + 128 + h*HDIM;

        ull acc[8];
        #pragma unroll
        for (int j = 0; j < 8; j++) acc[j] = 0ull;
        float ssum = 0.f;

        #pragma unroll 2
        for (int k = 0; k < NS; k++) {
            const ulonglong2* kp = (const ulonglong2*)(kbase + k*192);
            ull d2 = 0ull;
            #pragma unroll
            for (int j = 0; j < 4; j++) {
                ulonglong2 kv = kp[j];
                FMA2(d2, qv[2*j],   kv.x, d2);
                FMA2(d2, qv[2*j+1], kv.y, d2);
            }
            float lo, hi;
            UNPACK2(lo, hi, d2);
            float e = exp2f(lo + hi);
            ssum += e;
            ull e2; PACK2(e2, e, e);
            const ulonglong2* vp = (const ulonglong2*)(vbase + k*192);
            #pragma unroll
            for (int j = 0; j < 4; j++) {
                ulonglong2 vv = vp[j];
                FMA2(acc[2*j],   e2, vv.x, acc[2*j]);
                FMA2(acc[2*j+1], e2, vv.y, acc[2*j+1]);
            }
        }
        float inv = 1.f / ssum;
        float* ct = sTokT + (h*HDIM)*88;
        #pragma unroll
        for (int j = 0; j < 8; j++) {
            float lo, hi;
            UNPACK2(lo, hi, acc[j]);
            ct[(2*j)*88 + q]   = lo * inv;
            ct[(2*j+1)*88 + q] = hi * inv;
        }
    }
    __syncthreads();

    // ---- phase 4: attn_out = ctx @ Wa + ba, 8x4 tiles; Wa from L2 ----
    float* sAO = sQKV;
    if (tid < 176) {
        int oct = tid >> 4;
        int n4  = (tid & 15) * 4;
        ulonglong2 bb = *(const ulonglong2*)(sba + n4);
        ull acc[8][2];
        #pragma unroll
        for (int r = 0; r < 8; r++) { acc[r][0] = bb.x; acc[r][1] = bb.y; }
        const float* tb0 = sTokT + oct*8;
        ulonglong2 wc_ = __ldg((const ulonglong2*)(Wa + n4));
        float4 ta = *(const float4*)(tb0);
        float4 tc = *(const float4*)(tb0 + 4);
        #pragma unroll 4
        for (int k = 0; k < 64; k++) {
            ulonglong2 wn; float4 tna, tnc;
            if (k < 63) {
                wn  = __ldg((const ulonglong2*)(Wa + (k+1)*64 + n4));
                tna = *(const float4*)(tb0 + (k+1)*88);
                tnc = *(const float4*)(tb0 + (k+1)*88 + 4);
            }
            ull tp[8];
            PACK2(tp[0], ta.x, ta.x); PACK2(tp[1], ta.y, ta.y);
            PACK2(tp[2], ta.z, ta.z); PACK2(tp[3], ta.w, ta.w);
            PACK2(tp[4], tc.x, tc.x); PACK2(tp[5], tc.y, tc.y);
            PACK2(tp[6], tc.z, tc.z); PACK2(tp[7], tc.w, tc.w);
            #pragma unroll
            for (int r = 0; r < 8; r++) {
                FMA2(acc[r][0], tp[r], wc_.x, acc[r][0]);
                FMA2(acc[r][1], tp[r], wc_.y, acc[r][1]);
            }
            wc_ = wn; ta = tna; tc = tnc;
        }
        #pragma unroll
        for (int r = 0; r < 8; r++)
            *(ulonglong2*)(sAO + (oct*8 + r)*64 + n4) =
                make_ulonglong2(acc[r][0], acc[r][1]);
    }
    __syncthreads();

    // ---- phase 5a: quartered pooling partials (uniform barriers) ----
    {
        int d  = tid & 63;
        int sq = tid >> 6;          // 0..5
        float accg = 0.f, accr[NR];
        #pragma unroll
        for (int j = 0; j < NR; j++) accr[j] = 0.f;
        if (sq < 4) {
            int s0 = sq * 22;
            int s1 = (sq == 3) ? NS : s0 + 22;
            for (int s = s0; s < s1; s++) {
                float v = sAO[s*64 + d];
                int r = (int)sRid[s];
                accg += v;
                #pragma unroll
                for (int j = 0; j < NR; j++)
                    accr[j] += (r == j) ? v : 0.f;
            }
        }
        float* pp = sPart + (sq & 1)*512 + d;
        if (sq < 2) {
            pp[0] = accg;
            #pragma unroll
            for (int j = 0; j < NR; j++) pp[(1 + j)*64] = accr[j];
        }
        __syncthreads();
        if (sq >= 2 && sq < 4) {
            atomicAdd(&pp[0], accg);
            #pragma unroll
            for (int j = 0; j < NR; j++) atomicAdd(&pp[(1 + j)*64], accr[j]);
        }
    }
    __syncthreads();

    // ---- phase 5b: finalize concat (512) ----
    for (int i = tid; i < 512; i += NT) {
        int g = i >> 6;
        float s = sPart[i] + sPart[512 + i];
        sCat[i] = (g == 0) ? s * (1.f / 86.f) : s / sCnt[g - 1];
    }
    __syncthreads();

    // ---- phase 6: out = relu(concat @ Wo + bo), float4 Wo loads (L2) ----
    if (tid < 256) {
        int ic = tid >> 5;          // 0..7, i-chunk of 64
        int cg = tid & 31;          // col group, j = 4*cg
        const float4* wp = (const float4*)(Wo + (size_t)(ic*64)*128) + cg;
        float a0 = 0.f, a1 = 0.f, a2 = 0.f, a3 = 0.f;
        #pragma unroll 8
        for (int i = 0; i < 64; i++) {
            float c = sCat[ic*64 + i];
            float4 w = __ldg(wp + (size_t)i * 32);
            a0 = fmaf(c, w.x, a0); a1 = fmaf(c, w.y, a1);
            a2 = fmaf(c, w.z, a2); a3 = fmaf(c, w.w, a3);
        }
        *(float4*)(sPart + ic*128 + cg*4) = make_float4(a0, a1, a2, a3);
    }
    __syncthreads();
    if (tid < 128) {
        float acc = bo[tid];
        #pragma unroll
        for (int ic = 0; ic < 8; ic++) acc += sPart[ic*128 + tid];
        out[(size_t)b * 128 + tid] = fmaxf(acc, 0.f);
    }
}

extern "C" void kernel_launch(void* const* d_in, const int* in_sizes, int n_in,
                              void* d_out, int out_size)
{
    const float* infl  = (const float*)d_in[0];
    const float* statf = (const float*)d_in[1];
    const float* Wc    = (const float*)d_in[2];
    const float* bc    = (const float*)d_in[3];
    const float* Wqkv  = (const float*)d_in[4];
    const float* bqkv  = (const float*)d_in[5];
    const float* Wa    = (const float*)d_in[6];
    const float* ba    = (const float*)d_in[7];
    const float* Wo    = (const float*)d_in[8];
    const float* bo    = (const float*)d_in[9];
    float* out = (float*)d_out;

    int B = in_sizes[0] / BINF;
    size_t smem = SMEM_FLOATS * sizeof(float);
    cudaFuncSetAttribute(country_attn_kernel,
                         cudaFuncAttributeMaxDynamicSharedMemorySize, (int)smem);
    country_attn_kernel<<<B, NT, smem>>>(infl, statf, Wc, bc, Wqkv, bqkv,
                                         Wa, ba, Wo, bo, out);
}

// round 17
// speedup vs baseline: 1.3215x; 1.0652x over previous
#include <cuda_runtime.h>

typedef unsigned long long ull;

#define FMA2(d, a, bb, c) \
    asm("fma.rn.f32x2 %0, %1, %2, %3;" : "=l"(d) : "l"(a), "l"(bb), "l"(c))
#define MUL2(d, a, bb) \
    asm("mul.rn.f32x2 %0, %1, %2;" : "=l"(d) : "l"(a), "l"(bb))
#define PACK2(d, lo, hi) \
    asm("mov.b64 %0, {%1, %2};" : "=l"(d) : "f"(lo), "f"(hi))
#define UNPACK2(lo, hi, s) \
    asm("mov.b64 {%0, %1}, %2;" : "=f"(lo), "=f"(hi) : "l"(s))

#define NS   86
#define DM   64
#define NH   4
#define HDIM 16
#define NFEAT 11
#define NR   7
#define NT   384
#define BINF (2*NS)

// smem float offsets (Wqkv / Wa streamed from L2, not staged)
#define OFF_WC    0        // 832
#define OFF_BC    832      // 64
#define OFF_BQKV  896      // 192
#define OFF_BA    1088     // 64
#define OFF_STAT  1152     // 948
#define OFF_INF   2100     // 172
#define OFF_RID   2272     // 88
#define OFF_CNT   2360     // 8
#define OFF_TOK   2368     // tokT / ctxT: 64*88 = 5632
#define OFF_QKV   8000     // 88*192 = 16896 (reused as attn_out)
#define OFF_CAT   24896    // 512
#define OFF_PART  25408    // 1024
#define SMEM_FLOATS 26432  // 105.7 KB -> 2 CTAs/SM (24 warps)

// 0.25f * log2(e): folds the 1/sqrt(HDIM) scale and the exp->exp2
// conversion into the q pre-scale, so softmax exp is a bare MUFU.EX2.
#define QSCALE 0.3606737602222409f

__global__ __launch_bounds__(NT, 2)
void country_attn_kernel(const float* __restrict__ infl,
                         const float* __restrict__ statf,
                         const float* __restrict__ Wc,
                         const float* __restrict__ bc,
                         const float* __restrict__ Wqkv,
                         const float* __restrict__ bqkv,
                         const float* __restrict__ Wa,
                         const float* __restrict__ ba,
                         const float* __restrict__ Wo,
                         const float* __restrict__ bo,
                         float* __restrict__ out)
{
    extern __shared__ float sm[];
    float* sWc   = sm + OFF_WC;
    float* sbc   = sm + OFF_BC;
    float* sbqkv = sm + OFF_BQKV;
    float* sba   = sm + OFF_BA;
    float* sStat = sm + OFF_STAT;
    float* sInf  = sm + OFF_INF;
    float* sRid  = sm + OFF_RID;
    float* sCnt  = sm + OFF_CNT;
    float* sTokT = sm + OFF_TOK;   // tokT[d][s], stride 88; later ctxT[d][q]
    float* sQKV  = sm + OFF_QKV;   // qkv[row][col], 88 x 192
    float* sCat  = sm + OFF_CAT;
    float* sPart = sm + OFF_PART;

    const int tid = threadIdx.x;
    const int b   = blockIdx.x;

    // ---- stage small weights / per-sample inputs ----
    {
        const float4* src = (const float4*)Wc; float4* dst = (float4*)sWc;
        for (int i = tid; i < 13*16; i += NT) dst[i] = src[i];
    }
    for (int i = tid; i < NS*NFEAT; i += NT) sStat[i] = statf[i];
    for (int i = tid; i < BINF; i += NT) sInf[i] = infl[(size_t)b * BINF + i];
    if (tid < 64)  { sbc[tid] = bc[tid]; sba[tid] = ba[tid]; }
    if (tid >= 64 && tid < 256) sbqkv[tid - 64] = bqkv[tid - 64];
    __syncthreads();

    // region id per token + counts
    if (tid < NS) {
        float r = 0.f;
        #pragma unroll
        for (int j = 0; j < NR; j++)
            if (sStat[tid*NFEAT + 2 + j] > 0.5f) r = (float)j;
        sRid[tid] = r;
    }
    if (tid >= 96 && tid < 96 + NR) {
        int rr = tid - 96;
        float c = 0.f;
        for (int s = 0; s < NS; s++)
            c += (sStat[s*NFEAT + 2 + rr] > 0.5f) ? 1.f : 0.f;
        sCnt[rr] = fmaxf(c, 1.f);
    }
    // zero pad cols s=86,87 of tokT
    if (tid >= 128 && tid < 256) {
        int t = tid - 128;
        sTokT[(t >> 1)*88 + 86 + (t & 1)] = 0.f;
    }

    // ---- phase 1: tokT[d][s] = relu(feats @ Wc + bc)^T ----
    for (int u = tid; u < NS*8; u += NT) {
        int d0 = (u / 86) * 8;
        int s  = u % 86;
        float f[13];
        f[0] = sInf[s] * 0.1f;
        f[1] = sInf[NS + s] * 0.1f;
        #pragma unroll
        for (int j = 0; j < NFEAT; j++) f[2 + j] = sStat[s*NFEAT + j];
        float4 b0 = *(const float4*)(sbc + d0);
        float4 b1 = *(const float4*)(sbc + d0 + 4);
        float acc[8] = {b0.x,b0.y,b0.z,b0.w, b1.x,b1.y,b1.z,b1.w};
        #pragma unroll
        for (int r = 0; r < 13; r++) {
            float4 w0 = *(const float4*)(sWc + r*64 + d0);
            float4 w1 = *(const float4*)(sWc + r*64 + d0 + 4);
            acc[0] = fmaf(f[r], w0.x, acc[0]); acc[1] = fmaf(f[r], w0.y, acc[1]);
            acc[2] = fmaf(f[r], w0.z, acc[2]); acc[3] = fmaf(f[r], w0.w, acc[3]);
            acc[4] = fmaf(f[r], w1.x, acc[4]); acc[5] = fmaf(f[r], w1.y, acc[5]);
            acc[6] = fmaf(f[r], w1.z, acc[6]); acc[7] = fmaf(f[r], w1.w, acc[7]);
        }
        #pragma unroll
        for (int j = 0; j < 8; j++)
            sTokT[(d0 + j)*88 + s] = fmaxf(acc[j], 0.f);
    }
    __syncthreads();

    // ---- phase 2: qkv = tokens @ Wqkv + bqkv, 12-row x 4-col tiles ----
    // 8 row-groups x 48 col-groups = 384 units: perfect one-pass balance.
    // Row-group 7 spans rows 84..95: out-of-range loads read harmless smem
    // garbage; stores guarded to rows < 88 (rows 86/87 are sQKV padding).
    {
        int grp = tid / 48;          // 0..7
        int n4  = (tid % 48) * 4;
        ulonglong2 bb = *(const ulonglong2*)(sbqkv + n4);
        ull acc[12][2];
        #pragma unroll
        for (int r = 0; r < 12; r++) { acc[r][0] = bb.x; acc[r][1] = bb.y; }
        const float* tb0 = sTokT + grp*12;
        ulonglong2 w_cur = __ldg((const ulonglong2*)(Wqkv + n4));
        #pragma unroll 2
        for (int k = 0; k < 64; k++) {
            ulonglong2 w_nx;
            if (k < 63)
                w_nx = __ldg((const ulonglong2*)(Wqkv + (k+1)*192 + n4));
            #pragma unroll
            for (int g = 0; g < 3; g++) {
                float4 t = *(const float4*)(tb0 + k*88 + g*4);
                ull tp0, tp1, tp2, tp3;
                PACK2(tp0, t.x, t.x); PACK2(tp1, t.y, t.y);
                PACK2(tp2, t.z, t.z); PACK2(tp3, t.w, t.w);
                FMA2(acc[g*4+0][0], tp0, w_cur.x, acc[g*4+0][0]);
                FMA2(acc[g*4+0][1], tp0, w_cur.y, acc[g*4+0][1]);
                FMA2(acc[g*4+1][0], tp1, w_cur.x, acc[g*4+1][0]);
                FMA2(acc[g*4+1][1], tp1, w_cur.y, acc[g*4+1][1]);
                FMA2(acc[g*4+2][0], tp2, w_cur.x, acc[g*4+2][0]);
                FMA2(acc[g*4+2][1], tp2, w_cur.y, acc[g*4+2][1]);
                FMA2(acc[g*4+3][0], tp3, w_cur.x, acc[g*4+3][0]);
                FMA2(acc[g*4+3][1], tp3, w_cur.y, acc[g*4+3][1]);
            }
            w_cur = w_nx;
        }
        int base = grp*12;
        #pragma unroll
        for (int r = 0; r < 12; r++) {
            if (base + r < 88)
                *(ulonglong2*)(sQKV + (base + r)*192 + n4) =
                    make_ulonglong2(acc[r][0], acc[r][1]);
        }
    }
    __syncthreads();

    // ---- phase 3: attention (packed f32x2). unit = (head, query): 344 units,
    //      ONE pass at 384 threads; h-major so warps share K/V rows (broadcast).
    if (tid < 344) {
        int h = tid / 86;
        int q = tid - h*86;

        ull qsc; PACK2(qsc, QSCALE, QSCALE);
        const ulonglong2* qp = (const ulonglong2*)(sQKV + q*192 + h*HDIM);
        ull qv[8];
        #pragma unroll
        for (int j = 0; j < 4; j++) {
            ulonglong2 a0 = qp[j];
            MUL2(qv[2*j],   a0.x, qsc);
            MUL2(qv[2*j+1], a0.y, qsc);
        }

        const float* kbase = sQKV + 64  + h*HDIM;
        const float* vbase = sQKV + 128 + h*HDIM;

        ull acc[8];
        #pragma unroll
        for (int j = 0; j < 8; j++) acc[j] = 0ull;
        float ssum = 0.f;

        #pragma unroll 2
        for (int k = 0; k < NS; k++) {
            const ulonglong2* kp = (const ulonglong2*)(kbase + k*192);
            ull d2 = 0ull;
            #pragma unroll
            for (int j = 0; j < 4; j++) {
                ulonglong2 kv = kp[j];
                FMA2(d2, qv[2*j],   kv.x, d2);
                FMA2(d2, qv[2*j+1], kv.y, d2);
            }
            float lo, hi;
            UNPACK2(lo, hi, d2);
            float e = exp2f(lo + hi);
            ssum += e;
            ull e2; PACK2(e2, e, e);
            const ulonglong2* vp = (const ulonglong2*)(vbase + k*192);
            #pragma unroll
            for (int j = 0; j < 4; j++) {
                ulonglong2 vv = vp[j];
                FMA2(acc[2*j],   e2, vv.x, acc[2*j]);
                FMA2(acc[2*j+1], e2, vv.y, acc[2*j+1]);
            }
        }
        float inv = 1.f / ssum;
        float* ct = sTokT + (h*HDIM)*88;
        #pragma unroll
        for (int j = 0; j < 8; j++) {
            float lo, hi;
            UNPACK2(lo, hi, acc[j]);
            ct[(2*j)*88 + q]   = lo * inv;
            ct[(2*j+1)*88 + q] = hi * inv;
        }
    }
    __syncthreads();

    // ---- phase 4: attn_out = ctx @ Wa + ba, 4-row x 4-col tiles ----
    // 22 quads x 16 col-groups = 352 units, one pass, 11/12 warps active.
    float* sAO = sQKV;
    if (tid < 352) {
        int quad = tid >> 4;         // 0..21
        int n4   = (tid & 15) * 4;
        ulonglong2 bb = *(const ulonglong2*)(sba + n4);
        ull acc[4][2];
        #pragma unroll
        for (int r = 0; r < 4; r++) { acc[r][0] = bb.x; acc[r][1] = bb.y; }
        const float* tb0 = sTokT + quad*4;
        ulonglong2 w_cur = __ldg((const ulonglong2*)(Wa + n4));
        float4 ta = *(const float4*)(tb0);
        #pragma unroll 4
        for (int k = 0; k < 64; k++) {
            ulonglong2 w_nx; float4 tna;
            if (k < 63) {
                w_nx = __ldg((const ulonglong2*)(Wa + (k+1)*64 + n4));
                tna  = *(const float4*)(tb0 + (k+1)*88);
            }
            ull tp0, tp1, tp2, tp3;
            PACK2(tp0, ta.x, ta.x); PACK2(tp1, ta.y, ta.y);
            PACK2(tp2, ta.z, ta.z); PACK2(tp3, ta.w, ta.w);
            FMA2(acc[0][0], tp0, w_cur.x, acc[0][0]);
            FMA2(acc[0][1], tp0, w_cur.y, acc[0][1]);
            FMA2(acc[1][0], tp1, w_cur.x, acc[1][0]);
            FMA2(acc[1][1], tp1, w_cur.y, acc[1][1]);
            FMA2(acc[2][0], tp2, w_cur.x, acc[2][0]);
            FMA2(acc[2][1], tp2, w_cur.y, acc[2][1]);
            FMA2(acc[3][0], tp3, w_cur.x, acc[3][0]);
            FMA2(acc[3][1], tp3, w_cur.y, acc[3][1]);
            w_cur = w_nx; ta = tna;
        }
        #pragma unroll
        for (int r = 0; r < 4; r++)
            *(ulonglong2*)(sAO + (quad*4 + r)*64 + n4) =
                make_ulonglong2(acc[r][0], acc[r][1]);
    }
    __syncthreads();

    // ---- phase 5a: quartered pooling partials (uniform barriers) ----
    {
        int d  = tid & 63;
        int sq = tid >> 6;          // 0..5
        float accg = 0.f, accr[NR];
        #pragma unroll
        for (int j = 0; j < NR; j++) accr[j] = 0.f;
        if (sq < 4) {
            int s0 = sq * 22;
            int s1 = (sq == 3) ? NS : s0 + 22;
            for (int s = s0; s < s1; s++) {
                float v = sAO[s*64 + d];
                int r = (int)sRid[s];
                accg += v;
                #pragma unroll
                for (int j = 0; j < NR; j++)
                    accr[j] += (r == j) ? v : 0.f;
            }
        }
        float* pp = sPart + (sq & 1)*512 + d;
        if (sq < 2) {
            pp[0] = accg;
            #pragma unroll
            for (int j = 0; j < NR; j++) pp[(1 + j)*64] = accr[j];
        }
        __syncthreads();
        if (sq >= 2 && sq < 4) {
            atomicAdd(&pp[0], accg);
            #pragma unroll
            for (int j = 0; j < NR; j++) atomicAdd(&pp[(1 + j)*64], accr[j]);
        }
    }
    __syncthreads();

    // ---- phase 5b: finalize concat (512) ----
    for (int i = tid; i < 512; i += NT) {
        int g = i >> 6;
        float s = sPart[i] + sPart[512 + i];
        sCat[i] = (g == 0) ? s * (1.f / 86.f) : s / sCnt[g - 1];
    }
    __syncthreads();

    // ---- phase 6: out = relu(concat @ Wo + bo), float4 Wo loads (L2) ----
    if (tid < 256) {
        int ic = tid >> 5;          // 0..7, i-chunk of 64
        int cg = tid & 31;          // col group, j = 4*cg
        const float4* wp = (const float4*)(Wo + (size_t)(ic*64)*128) + cg;
        float a0 = 0.f, a1 = 0.f, a2 = 0.f, a3 = 0.f;
        #pragma unroll 8
        for (int i = 0; i < 64; i++) {
            float c = sCat[ic*64 + i];
            float4 w = __ldg(wp + (size_t)i * 32);
            a0 = fmaf(c, w.x, a0); a1 = fmaf(c, w.y, a1);
            a2 = fmaf(c, w.z, a2); a3 = fmaf(c, w.w, a3);
        }
        *(float4*)(sPart + ic*128 + cg*4) = make_float4(a0, a1, a2, a3);
    }
    __syncthreads();
    if (tid < 128) {
        float acc = bo[tid];
        #pragma unroll
        for (int ic = 0; ic < 8; ic++) acc += sPart[ic*128 + tid];
        out[(size_t)b * 128 + tid] = fmaxf(acc, 0.f);
    }
}

extern "C" void kernel_launch(void* const* d_in, const int* in_sizes, int n_in,
                              void* d_out, int out_size)
{
    const float* infl  = (const float*)d_in[0];
    const float* statf = (const float*)d_in[1];
    const float* Wc    = (const float*)d_in[2];
    const float* bc    = (const float*)d_in[3];
    const float* Wqkv  = (const float*)d_in[4];
    const float* bqkv  = (const float*)d_in[5];
    const float* Wa    = (const float*)d_in[6];
    const float* ba    = (const float*)d_in[7];
    const float* Wo    = (const float*)d_in[8];
    const float* bo    = (const float*)d_in[9];
    float* out = (float*)d_out;

    int B = in_sizes[0] / BINF;
    size_t smem = SMEM_FLOATS * sizeof(float);
    cudaFuncSetAttribute(country_attn_kernel,
                         cudaFuncAttributeMaxDynamicSharedMemorySize, (int)smem);
    country_attn_kernel<<<B, NT, smem>>>(infl, statf, Wc, bc, Wqkv, bqkv,
                                         Wa, ba, Wo, bo, out);
}